// round 9
// baseline (speedup 1.0000x reference)
#include <cuda_runtime.h>
#include <cuda_bf16.h>
#include <math.h>
#include <cstdint>

// ============================================================================
// MHA: out = softmax((XqWq)(XkWk)^T / sqrt(Hd)) (XvWv)
// B=8, S=1024, D=1024, H=16, Hd=64, fp32 in/out. Plain sm_100 (no tcgen05).
//
// Round 9: GEMM gets a true cp.async double-buffer pipeline (all operands
// bf16, fill off the critical path). A-conversion un-fused back into
// convert_split so the GEMM streams bf16 only. Lambda fill (R8-proven),
// no macros. Flash attention identical to the R8 passing kernel.
// ============================================================================

#define MHA_M   8192
#define MHA_D   1024
#define MHA_H   16
#define MHA_S   1024

__device__ __nv_bfloat16 g_Qhi[MHA_M * MHA_D];
__device__ __nv_bfloat16 g_Qlo[MHA_M * MHA_D];
__device__ __nv_bfloat16 g_Khi[MHA_M * MHA_D];
__device__ __nv_bfloat16 g_Klo[MHA_M * MHA_D];
__device__ __nv_bfloat16 g_Vhi[MHA_M * MHA_D];
__device__ __nv_bfloat16 g_Vlo[MHA_M * MHA_D];
__device__ __nv_bfloat16 g_Ahi[MHA_M * MHA_D];
__device__ __nv_bfloat16 g_Alo[MHA_M * MHA_D];
__device__ __nv_bfloat16 g_Bhi[MHA_D * MHA_D];   // W^T, [N][K]
__device__ __nv_bfloat16 g_Blo[MHA_D * MHA_D];

// ---------------------------------------------------------------------------
// helpers
// ---------------------------------------------------------------------------
__device__ __forceinline__ uint32_t smem_to_u32(const void* p) {
    uint32_t a;
    asm("{ .reg .u64 t; cvta.to.shared.u64 t, %1; cvt.u32.u64 %0, t; }"
        : "=r"(a) : "l"(p));
    return a;
}
__device__ __forceinline__ void ldm4(uint32_t* r, uint32_t addr) {
    asm volatile("ldmatrix.sync.aligned.m8n8.x4.shared.b16 {%0,%1,%2,%3}, [%4];"
                 : "=r"(r[0]), "=r"(r[1]), "=r"(r[2]), "=r"(r[3]) : "r"(addr));
}
__device__ __forceinline__ void mma_bf16(float* d, const uint32_t* a,
                                         const uint32_t* b) {
    asm volatile(
        "mma.sync.aligned.m16n8k16.row.col.f32.bf16.bf16.f32 "
        "{%0,%1,%2,%3}, {%4,%5,%6,%7}, {%8,%9}, {%0,%1,%2,%3};"
        : "+f"(d[0]), "+f"(d[1]), "+f"(d[2]), "+f"(d[3])
        : "r"(a[0]), "r"(a[1]), "r"(a[2]), "r"(a[3]), "r"(b[0]), "r"(b[1]));
}
__device__ __forceinline__ uint32_t packbf(float x, float y) {
    __nv_bfloat162 t = __floats2bfloat162_rn(x, y);
    return *reinterpret_cast<uint32_t*>(&t);
}
__device__ __forceinline__ float bfres(float x) {
    return x - __bfloat162float(__float2bfloat16_rn(x));
}
__device__ __forceinline__ void cp_async16(uint32_t saddr, const void* gaddr) {
    asm volatile("cp.async.cg.shared.global [%0], [%1], 16;"
                 :: "r"(saddr), "l"(gaddr));
}
__device__ __forceinline__ void cp_async_commit() {
    asm volatile("cp.async.commit_group;");
}
__device__ __forceinline__ void cp_async_wait0() {
    asm volatile("cp.async.wait_group 0;");
}

// ---------------------------------------------------------------------------
// fp32 -> bf16 hi/lo split (inputs)
// ---------------------------------------------------------------------------
__global__ void convert_split(const float* __restrict__ X,
                              __nv_bfloat16* __restrict__ hi,
                              __nv_bfloat16* __restrict__ lo, int n)
{
    int i = (blockIdx.x * blockDim.x + threadIdx.x) * 4;
    if (i >= n) return;
    float4 v = *(const float4*)(X + i);
    __nv_bfloat16 h0 = __float2bfloat16(v.x);
    __nv_bfloat16 h1 = __float2bfloat16(v.y);
    __nv_bfloat16 h2 = __float2bfloat16(v.z);
    __nv_bfloat16 h3 = __float2bfloat16(v.w);
    __nv_bfloat16 l0 = __float2bfloat16(v.x - __bfloat162float(h0));
    __nv_bfloat16 l1 = __float2bfloat16(v.y - __bfloat162float(h1));
    __nv_bfloat16 l2 = __float2bfloat16(v.z - __bfloat162float(h2));
    __nv_bfloat16 l3 = __float2bfloat16(v.w - __bfloat162float(h3));
    *(__nv_bfloat162*)(hi + i)     = __nv_bfloat162(h0, h1);
    *(__nv_bfloat162*)(hi + i + 2) = __nv_bfloat162(h2, h3);
    *(__nv_bfloat162*)(lo + i)     = __nv_bfloat162(l0, l1);
    *(__nv_bfloat162*)(lo + i + 2) = __nv_bfloat162(l2, l3);
}

// ---------------------------------------------------------------------------
// W [K,N] fp32 -> W^T [N,K] bf16 hi/lo
// ---------------------------------------------------------------------------
__global__ void transpose_split(const float* __restrict__ W,
                                __nv_bfloat16* __restrict__ hi,
                                __nv_bfloat16* __restrict__ lo, int Dm)
{
    __shared__ float t[32][33];
    const int bx = blockIdx.x * 32;
    const int by = blockIdx.y * 32;
    const int x = threadIdx.x, y = threadIdx.y;
#pragma unroll
    for (int j = 0; j < 4; ++j)
        t[y + 8 * j][x] = W[(size_t)(by + y + 8 * j) * Dm + bx + x];
    __syncthreads();
#pragma unroll
    for (int j = 0; j < 4; ++j) {
        float v = t[x][y + 8 * j];
        __nv_bfloat16 h = __float2bfloat16(v);
        __nv_bfloat16 l = __float2bfloat16(v - __bfloat162float(h));
        size_t o = (size_t)(bx + y + 8 * j) * Dm + by + x;
        hi[o] = h;
        lo[o] = l;
    }
}

// ---------------------------------------------------------------------------
// Projection GEMM: all-bf16 operands, cp.async double-buffer pipeline.
// CTA 128x128, BK=32, 128 threads = 4 warps (2x2 grid of 64x64 warp tiles).
// Epilogue writes bf16 hi/lo.
// ---------------------------------------------------------------------------
#define G_ROWB  48
#define G_SLAB  (128 * G_ROWB)          // 6144
#define G_T_AHI 0
#define G_T_ALO (2 * G_SLAB)
#define G_T_BHI (4 * G_SLAB)
#define G_T_BLO (6 * G_SLAB)
#define G_STAGE (8 * G_SLAB)            // 49152
#define GEMM_SMEM (2 * G_STAGE)         // 98304

__global__ __launch_bounds__(128, 2)
void gemm_pipe(const __nv_bfloat16* __restrict__ Ahi,
               const __nv_bfloat16* __restrict__ Alo,
               const __nv_bfloat16* __restrict__ Bhi,
               const __nv_bfloat16* __restrict__ Blo,
               __nv_bfloat16* __restrict__ Chi,
               __nv_bfloat16* __restrict__ Clo,
               int K, int Nout)
{
    extern __shared__ char smem[];
    const int tid = threadIdx.x;
    const int lane = tid & 31;
    const int wid = tid >> 5;
    const int warp_row = wid >> 1;      // 0..1
    const int warp_col = wid & 1;       // 0..1
    const int m0 = blockIdx.y * 128;
    const int n0 = blockIdx.x * 128;
    const uint32_t smem_base = smem_to_u32(smem);

    // chunk mapping: 4 chunks/thread; chunk = 8 bf16 of one row
    int rowC[4], c8[4];
    uint32_t sOffT[4];
#pragma unroll
    for (int i = 0; i < 4; ++i) {
        int ch = i * 128 + tid;
        rowC[i] = ch >> 2;
        c8[i] = ch & 3;
        sOffT[i] = (uint32_t)((c8[i] >> 1) * G_SLAB + rowC[i] * G_ROWB +
                              (c8[i] & 1) * 16);
    }

    // ldmatrix patterns (hardware-validated rounds 4-8)
    const uint32_t aLM = (uint32_t)((warp_row * 64 + (lane & 15)) * G_ROWB +
                                    (lane >> 4) * 16);
    const uint32_t bLM = (uint32_t)((warp_col * 64 + ((lane >> 4) << 3) +
                                     (lane & 7)) * G_ROWB +
                                    ((lane >> 3) & 1) * 16);

    // async stage fill: 16 cp.async of 16B per thread, zero register cost
    auto fill_stage = [&](int stage, int k0) {
        const uint32_t sb = smem_base + stage * G_STAGE;
#pragma unroll
        for (int i = 0; i < 4; ++i) {
            const size_t ga = (size_t)(m0 + rowC[i]) * K + k0 + c8[i] * 8;
            const size_t gb = (size_t)(n0 + rowC[i]) * K + k0 + c8[i] * 8;
            cp_async16(sb + G_T_AHI + sOffT[i], Ahi + ga);
            cp_async16(sb + G_T_ALO + sOffT[i], Alo + ga);
            cp_async16(sb + G_T_BHI + sOffT[i], Bhi + gb);
            cp_async16(sb + G_T_BLO + sOffT[i], Blo + gb);
        }
        cp_async_commit();
    };

    float acc[4][8][4];
#pragma unroll
    for (int mf = 0; mf < 4; ++mf)
#pragma unroll
        for (int nf = 0; nf < 8; ++nf)
#pragma unroll
            for (int q = 0; q < 4; ++q) acc[mf][nf][q] = 0.f;

    fill_stage(0, 0);
    cp_async_wait0();
    __syncthreads();

    const int T = K / 32;
    for (int t = 0; t < T; ++t) {
        const int cur = t & 1;

        // issue next stage before computing — fill runs under the MMAs
        if (t + 1 < T) fill_stage(cur ^ 1, (t + 1) * 32);

        const uint32_t sb = smem_base + cur * G_STAGE;
#pragma unroll
        for (int kf = 0; kf < 2; ++kf) {
            const uint32_t kfo = kf * G_SLAB;
            uint32_t ah[4][4], al[4][4];
#pragma unroll
            for (int mf = 0; mf < 4; ++mf) {
                ldm4(ah[mf], sb + G_T_AHI + kfo + aLM + mf * 16 * G_ROWB);
                ldm4(al[mf], sb + G_T_ALO + kfo + aLM + mf * 16 * G_ROWB);
            }
#pragma unroll
            for (int pr = 0; pr < 4; ++pr) {
                uint32_t rh[4], rl[4];
                ldm4(rh, sb + G_T_BHI + kfo + bLM + pr * 16 * G_ROWB);
                ldm4(rl, sb + G_T_BLO + kfo + bLM + pr * 16 * G_ROWB);
                uint32_t bh0[2] = {rh[0], rh[1]}, bh1[2] = {rh[2], rh[3]};
                uint32_t bl0[2] = {rl[0], rl[1]}, bl1[2] = {rl[2], rl[3]};
#pragma unroll
                for (int mf = 0; mf < 4; ++mf) {
                    mma_bf16(acc[mf][pr * 2], ah[mf], bh0);
                    mma_bf16(acc[mf][pr * 2], ah[mf], bl0);
                    mma_bf16(acc[mf][pr * 2], al[mf], bh0);
                    mma_bf16(acc[mf][pr * 2 + 1], ah[mf], bh1);
                    mma_bf16(acc[mf][pr * 2 + 1], ah[mf], bl1);
                    mma_bf16(acc[mf][pr * 2 + 1], al[mf], bh1);
                }
            }
        }

        if (t + 1 < T) cp_async_wait0();
        __syncthreads();
    }

    // epilogue: split fp32 acc -> bf16 hi/lo
    const int mBase = m0 + warp_row * 64 + (lane >> 2);
    const int nBase = n0 + warp_col * 64 + (lane & 3) * 2;
#pragma unroll
    for (int mf = 0; mf < 4; ++mf)
#pragma unroll
        for (int nf = 0; nf < 8; ++nf) {
            const int gm = mBase + mf * 16;
            const int gn = nBase + nf * 8;
            const float* a = acc[mf][nf];
            *(uint32_t*)&Chi[(size_t)gm * Nout + gn] = packbf(a[0], a[1]);
            *(uint32_t*)&Clo[(size_t)gm * Nout + gn] = packbf(bfres(a[0]), bfres(a[1]));
            *(uint32_t*)&Chi[(size_t)(gm + 8) * Nout + gn] = packbf(a[2], a[3]);
            *(uint32_t*)&Clo[(size_t)(gm + 8) * Nout + gn] = packbf(bfres(a[2]), bfres(a[3]));
        }
}

// ---------------------------------------------------------------------------
// Flash attention with mma.sync (identical to the round-8 passing kernel).
// ---------------------------------------------------------------------------
#define FM_ROWB 144
#define FM_SQHI 0
#define FM_SQLO (FM_SQHI + 128 * FM_ROWB)
#define FM_SKHI (FM_SQLO + 128 * FM_ROWB)
#define FM_SKLO (FM_SKHI + 64 * FM_ROWB)
#define FM_SVHI (FM_SKLO + 64 * FM_ROWB)
#define FM_SVLO (FM_SVHI + 64 * FM_ROWB)
#define FM_SMEM (FM_SVLO + 64 * FM_ROWB)     // 73728

__global__ __launch_bounds__(256, 2)
void flash_mma(const __nv_bfloat16* __restrict__ Qhi,
               const __nv_bfloat16* __restrict__ Qlo,
               const __nv_bfloat16* __restrict__ Khi,
               const __nv_bfloat16* __restrict__ Klo,
               const __nv_bfloat16* __restrict__ Vhi,
               const __nv_bfloat16* __restrict__ Vlo,
               float* __restrict__ Out, int S, int H)
{
    extern __shared__ char sm[];
    const uint32_t sb = smem_to_u32(sm);
    const int tid = threadIdx.x;
    const int lane = tid & 31;
    const int w = tid >> 5;
    const int D = H * 64;

    const int qblk = blockIdx.x;
    const int bh = blockIdx.y;
    const int b = bh / H;
    const int h = bh % H;

    const size_t qrow0 = (size_t)(b * S + qblk * 128);
    const size_t krow0 = (size_t)(b * S);

    const __nv_bfloat16* Qh = Qhi + qrow0 * D + h * 64;
    const __nv_bfloat16* Ql = Qlo + qrow0 * D + h * 64;

#pragma unroll
    for (int i = 0; i < 4; ++i) {
        const int ch = i * 256 + tid;
        const int row = ch >> 3;
        const int c = ch & 7;
        *(uint4*)(sm + FM_SQHI + row * FM_ROWB + c * 16) =
            *(const uint4*)(Qh + (size_t)row * D + c * 8);
        *(uint4*)(sm + FM_SQLO + row * FM_ROWB + c * 16) =
            *(const uint4*)(Ql + (size_t)row * D + c * 8);
    }

    const uint32_t aOff = (uint32_t)((w * 16 + (lane & 15)) * FM_ROWB +
                                     ((lane >> 4) << 4));
    const uint32_t bRow = ((lane >> 4) << 3) + (lane & 7);
    const uint32_t bSeg = ((lane >> 3) & 1) << 4;

    float o[8][4];
    float sacc[8][4];
#pragma unroll
    for (int nf = 0; nf < 8; ++nf)
#pragma unroll
        for (int q = 0; q < 4; ++q) o[nf][q] = 0.f;
    float m0v = -1e30f, m1v = -1e30f, l0v = 0.f, l1v = 0.f;

    const float qs = 0.125f * 1.4426950408889634f;
    const int nkv = S / 64;

    for (int kv = 0; kv < nkv; ++kv) {
        __syncthreads();
        {
            const __nv_bfloat16* Kh = Khi + (krow0 + kv * 64) * D + h * 64;
            const __nv_bfloat16* Kl = Klo + (krow0 + kv * 64) * D + h * 64;
            const __nv_bfloat16* Vh = Vhi + (krow0 + kv * 64) * D + h * 64;
            const __nv_bfloat16* Vl = Vlo + (krow0 + kv * 64) * D + h * 64;
#pragma unroll
            for (int i = 0; i < 2; ++i) {
                const int ch = i * 256 + tid;
                const int row = ch >> 3;
                const int c = ch & 7;
                *(uint4*)(sm + FM_SKHI + row * FM_ROWB + c * 16) =
                    *(const uint4*)(Kh + (size_t)row * D + c * 8);
                *(uint4*)(sm + FM_SKLO + row * FM_ROWB + c * 16) =
                    *(const uint4*)(Kl + (size_t)row * D + c * 8);
                uint4 vh = *(const uint4*)(Vh + (size_t)row * D + c * 8);
                uint4 vl = *(const uint4*)(Vl + (size_t)row * D + c * 8);
                const unsigned short* ph = (const unsigned short*)&vh;
                const unsigned short* pl = (const unsigned short*)&vl;
#pragma unroll
                for (int u = 0; u < 8; ++u) {
                    *(unsigned short*)(sm + FM_SVHI + (c * 8 + u) * FM_ROWB + row * 2) = ph[u];
                    *(unsigned short*)(sm + FM_SVLO + (c * 8 + u) * FM_ROWB + row * 2) = pl[u];
                }
            }
        }
        __syncthreads();

#pragma unroll
        for (int nf = 0; nf < 8; ++nf)
#pragma unroll
            for (int q = 0; q < 4; ++q) sacc[nf][q] = 0.f;

#pragma unroll
        for (int kf = 0; kf < 4; ++kf) {
            uint32_t ah[4], al[4];
            ldm4(ah, sb + FM_SQHI + aOff + kf * 32);
            ldm4(al, sb + FM_SQLO + aOff + kf * 32);
            uint32_t bh_[8][2], bl_[8][2];
#pragma unroll
            for (int pr = 0; pr < 4; ++pr) {
                uint32_t r[4];
                ldm4(r, sb + FM_SKHI + (pr * 16 + bRow) * FM_ROWB + kf * 32 + bSeg);
                bh_[pr * 2][0] = r[0]; bh_[pr * 2][1] = r[1];
                bh_[pr * 2 + 1][0] = r[2]; bh_[pr * 2 + 1][1] = r[3];
                ldm4(r, sb + FM_SKLO + (pr * 16 + bRow) * FM_ROWB + kf * 32 + bSeg);
                bl_[pr * 2][0] = r[0]; bl_[pr * 2][1] = r[1];
                bl_[pr * 2 + 1][0] = r[2]; bl_[pr * 2 + 1][1] = r[3];
            }
#pragma unroll
            for (int nf = 0; nf < 8; ++nf) {
                mma_bf16(sacc[nf], ah, bh_[nf]);
                mma_bf16(sacc[nf], ah, bl_[nf]);
                mma_bf16(sacc[nf], al, bh_[nf]);
            }
        }

        float rm0 = -1e30f, rm1 = -1e30f;
#pragma unroll
        for (int nf = 0; nf < 8; ++nf) {
#pragma unroll
            for (int q = 0; q < 4; ++q) sacc[nf][q] *= qs;
            rm0 = fmaxf(rm0, fmaxf(sacc[nf][0], sacc[nf][1]));
            rm1 = fmaxf(rm1, fmaxf(sacc[nf][2], sacc[nf][3]));
        }
        rm0 = fmaxf(rm0, __shfl_xor_sync(0xffffffffu, rm0, 1));
        rm0 = fmaxf(rm0, __shfl_xor_sync(0xffffffffu, rm0, 2));
        rm1 = fmaxf(rm1, __shfl_xor_sync(0xffffffffu, rm1, 1));
        rm1 = fmaxf(rm1, __shfl_xor_sync(0xffffffffu, rm1, 2));

        const float mn0 = fmaxf(m0v, rm0);
        const float mn1 = fmaxf(m1v, rm1);
        const float a0 = exp2f(m0v - mn0);
        const float a1 = exp2f(m1v - mn1);
        float rs0 = 0.f, rs1 = 0.f;
#pragma unroll
        for (int nf = 0; nf < 8; ++nf) {
            float p0 = exp2f(sacc[nf][0] - mn0);
            float p1 = exp2f(sacc[nf][1] - mn0);
            float p2 = exp2f(sacc[nf][2] - mn1);
            float p3 = exp2f(sacc[nf][3] - mn1);
            sacc[nf][0] = p0; sacc[nf][1] = p1;
            sacc[nf][2] = p2; sacc[nf][3] = p3;
            rs0 += p0 + p1;
            rs1 += p2 + p3;
        }
        rs0 += __shfl_xor_sync(0xffffffffu, rs0, 1);
        rs0 += __shfl_xor_sync(0xffffffffu, rs0, 2);
        rs1 += __shfl_xor_sync(0xffffffffu, rs1, 1);
        rs1 += __shfl_xor_sync(0xffffffffu, rs1, 2);
        l0v = l0v * a0 + rs0;
        l1v = l1v * a1 + rs1;
        m0v = mn0; m1v = mn1;
#pragma unroll
        for (int nf = 0; nf < 8; ++nf) {
            o[nf][0] *= a0; o[nf][1] *= a0;
            o[nf][2] *= a1; o[nf][3] *= a1;
        }

#pragma unroll
        for (int jf = 0; jf < 4; ++jf) {
            const float* p0 = sacc[2 * jf];
            const float* p1 = sacc[2 * jf + 1];
            uint32_t aph[4], apl[4];
            aph[0] = packbf(p0[0], p0[1]);
            aph[1] = packbf(p0[2], p0[3]);
            aph[2] = packbf(p1[0], p1[1]);
            aph[3] = packbf(p1[2], p1[3]);
            apl[0] = packbf(bfres(p0[0]), bfres(p0[1]));
            apl[1] = packbf(bfres(p0[2]), bfres(p0[3]));
            apl[2] = packbf(bfres(p1[0]), bfres(p1[1]));
            apl[3] = packbf(bfres(p1[2]), bfres(p1[3]));
#pragma unroll
            for (int pr = 0; pr < 4; ++pr) {
                uint32_t rv[4], rl[4];
                ldm4(rv, sb + FM_SVHI + (pr * 16 + bRow) * FM_ROWB + jf * 32 + bSeg);
                ldm4(rl, sb + FM_SVLO + (pr * 16 + bRow) * FM_ROWB + jf * 32 + bSeg);
                uint32_t bvh0[2] = {rv[0], rv[1]}, bvh1[2] = {rv[2], rv[3]};
                uint32_t bvl0[2] = {rl[0], rl[1]}, bvl1[2] = {rl[2], rl[3]};
                mma_bf16(o[pr * 2], aph, bvh0);
                mma_bf16(o[pr * 2], aph, bvl0);
                mma_bf16(o[pr * 2], apl, bvh0);
                mma_bf16(o[pr * 2 + 1], aph, bvh1);
                mma_bf16(o[pr * 2 + 1], aph, bvl1);
                mma_bf16(o[pr * 2 + 1], apl, bvh1);
            }
        }
    }

    const float inv0 = 1.f / l0v;
    const float inv1 = 1.f / l1v;
    const int r0 = lane >> 2;
    const int c2 = (lane & 3) * 2;
    float* O0 = Out + (qrow0 + w * 16 + r0) * D + h * 64;
#pragma unroll
    for (int nf = 0; nf < 8; ++nf) {
        *(float2*)(O0 + nf * 8 + c2) =
            make_float2(o[nf][0] * inv0, o[nf][1] * inv0);
        *(float2*)(O0 + (size_t)8 * D + nf * 8 + c2) =
            make_float2(o[nf][2] * inv1, o[nf][3] * inv1);
    }
}

// ----------------------------------------------------------------------------
// Launch
// ----------------------------------------------------------------------------
extern "C" void kernel_launch(void* const* d_in, const int* in_sizes, int n_in,
                              void* d_out, int out_size)
{
    const float* x[3] = {(const float*)d_in[0], (const float*)d_in[1],
                         (const float*)d_in[2]};
    const float* w[3] = {(const float*)d_in[3], (const float*)d_in[4],
                         (const float*)d_in[5]};
    float* out = (float*)d_out;

    const int D = MHA_D, M = MHA_M, S = MHA_S, H = MHA_H;
    const int B = M / S;

    __nv_bfloat16 *Qhi, *Qlo, *Khi, *Klo, *Vhi, *Vlo, *Ahi, *Alo, *Bhi, *Blo;
    cudaGetSymbolAddress((void**)&Qhi, g_Qhi);
    cudaGetSymbolAddress((void**)&Qlo, g_Qlo);
    cudaGetSymbolAddress((void**)&Khi, g_Khi);
    cudaGetSymbolAddress((void**)&Klo, g_Klo);
    cudaGetSymbolAddress((void**)&Vhi, g_Vhi);
    cudaGetSymbolAddress((void**)&Vlo, g_Vlo);
    cudaGetSymbolAddress((void**)&Ahi, g_Ahi);
    cudaGetSymbolAddress((void**)&Alo, g_Alo);
    cudaGetSymbolAddress((void**)&Bhi, g_Bhi);
    cudaGetSymbolAddress((void**)&Blo, g_Blo);

    __nv_bfloat16* outs_hi[3] = {Qhi, Khi, Vhi};
    __nv_bfloat16* outs_lo[3] = {Qlo, Klo, Vlo};

    cudaFuncSetAttribute(gemm_pipe,
                         cudaFuncAttributeMaxDynamicSharedMemorySize, GEMM_SMEM);
    cudaFuncSetAttribute(flash_mma,
                         cudaFuncAttributeMaxDynamicSharedMemorySize, FM_SMEM);

    const int nElem = M * D;
    for (int p = 0; p < 3; ++p) {
        convert_split<<<nElem / 4 / 256, 256>>>(x[p], Ahi, Alo, nElem);
        transpose_split<<<dim3(D / 32, D / 32), dim3(32, 8)>>>(w[p], Bhi, Blo, D);
        gemm_pipe<<<dim3(D / 128, M / 128), 128, GEMM_SMEM>>>(
            Ahi, Alo, Bhi, Blo, outs_hi[p], outs_lo[p], D, D);
    }

    dim3 fg(S / 128, B * H);
    flash_mma<<<fg, 256, FM_SMEM>>>(Qhi, Qlo, Khi, Klo, Vhi, Vlo, out, S, H);
}

// round 14
// speedup vs baseline: 1.1718x; 1.1718x over previous
#include <cuda_runtime.h>
#include <cuda_bf16.h>
#include <math.h>
#include <cstdint>

// ============================================================================
// MHA: out = softmax((XqWq)(XkWk)^T / sqrt(Hd)) (XvWv)
// B=8, S=1024, D=1024, H=16, Hd=64, fp32 in/out. Plain sm_100 (no tcgen05).
//
// Round 14: gemm_fused = R8 passing version (176us measured). Flash: Q kept
// in a persistent smem region (frags ldm4'd per iteration, R8-style register
// pressure) + double-buffered K/V with ONE __syncthreads per iteration and
// fill-after-compute. Smem 110592B, still 2 CTAs/SM.
// ============================================================================

#define MHA_M   8192
#define MHA_D   1024
#define MHA_H   16
#define MHA_S   1024

__device__ __nv_bfloat16 g_Qhi[MHA_M * MHA_D];
__device__ __nv_bfloat16 g_Qlo[MHA_M * MHA_D];
__device__ __nv_bfloat16 g_Khi[MHA_M * MHA_D];
__device__ __nv_bfloat16 g_Klo[MHA_M * MHA_D];
__device__ __nv_bfloat16 g_Vhi[MHA_M * MHA_D];
__device__ __nv_bfloat16 g_Vlo[MHA_M * MHA_D];
__device__ __nv_bfloat16 g_Bhi[MHA_D * MHA_D];   // W^T, [N][K]
__device__ __nv_bfloat16 g_Blo[MHA_D * MHA_D];

// ---------------------------------------------------------------------------
// helpers
// ---------------------------------------------------------------------------
__device__ __forceinline__ uint32_t smem_to_u32(const void* p) {
    uint32_t a;
    asm("{ .reg .u64 t; cvta.to.shared.u64 t, %1; cvt.u32.u64 %0, t; }"
        : "=r"(a) : "l"(p));
    return a;
}
__device__ __forceinline__ void ldm4(uint32_t* r, uint32_t addr) {
    asm volatile("ldmatrix.sync.aligned.m8n8.x4.shared.b16 {%0,%1,%2,%3}, [%4];"
                 : "=r"(r[0]), "=r"(r[1]), "=r"(r[2]), "=r"(r[3]) : "r"(addr));
}
__device__ __forceinline__ void mma_bf16(float* d, const uint32_t* a,
                                         const uint32_t* b) {
    asm volatile(
        "mma.sync.aligned.m16n8k16.row.col.f32.bf16.bf16.f32 "
        "{%0,%1,%2,%3}, {%4,%5,%6,%7}, {%8,%9}, {%0,%1,%2,%3};"
        : "+f"(d[0]), "+f"(d[1]), "+f"(d[2]), "+f"(d[3])
        : "r"(a[0]), "r"(a[1]), "r"(a[2]), "r"(a[3]), "r"(b[0]), "r"(b[1]));
}
__device__ __forceinline__ uint32_t packbf(float x, float y) {
    __nv_bfloat162 t = __floats2bfloat162_rn(x, y);
    return *reinterpret_cast<uint32_t*>(&t);
}
__device__ __forceinline__ float bfres(float x) {
    return x - __bfloat162float(__float2bfloat16_rn(x));
}

// ---------------------------------------------------------------------------
// W [K,N] fp32 -> W^T [N,K] bf16 hi/lo
// ---------------------------------------------------------------------------
__global__ void transpose_split(const float* __restrict__ W,
                                __nv_bfloat16* __restrict__ hi,
                                __nv_bfloat16* __restrict__ lo, int Dm)
{
    __shared__ float t[32][33];
    const int bx = blockIdx.x * 32;
    const int by = blockIdx.y * 32;
    const int x = threadIdx.x, y = threadIdx.y;
#pragma unroll
    for (int j = 0; j < 4; ++j)
        t[y + 8 * j][x] = W[(size_t)(by + y + 8 * j) * Dm + bx + x];
    __syncthreads();
#pragma unroll
    for (int j = 0; j < 4; ++j) {
        float v = t[x][y + 8 * j];
        __nv_bfloat16 h = __float2bfloat16(v);
        __nv_bfloat16 l = __float2bfloat16(v - __bfloat162float(h));
        size_t o = (size_t)(bx + y + 8 * j) * Dm + by + x;
        hi[o] = h;
        lo[o] = l;
    }
}

// ---------------------------------------------------------------------------
// Projection GEMM (identical to the R8 passing kernel, 176us measured).
// A = fp32 X (converted to hi/lo in-kernel), B = bf16 hi/lo.
// CTA 128x128, BK=32, 128 threads = 4 warps (2x2 grid of 64x64 warp tiles).
// ---------------------------------------------------------------------------
#define G_ROWB  48
#define G_SLAB  (128 * G_ROWB)          // 6144
#define G_T_AHI 0
#define G_T_ALO (2 * G_SLAB)
#define G_T_BHI (4 * G_SLAB)
#define G_T_BLO (6 * G_SLAB)
#define G_STAGE (8 * G_SLAB)            // 49152
#define GEMM_SMEM (2 * G_STAGE)         // 98304

__global__ __launch_bounds__(128, 2)
void gemm_fused(const float* __restrict__ X,
                const __nv_bfloat16* __restrict__ Bhi,
                const __nv_bfloat16* __restrict__ Blo,
                __nv_bfloat16* __restrict__ Chi,
                __nv_bfloat16* __restrict__ Clo,
                int K, int Nout)
{
    extern __shared__ char smem[];
    const int tid = threadIdx.x;
    const int lane = tid & 31;
    const int wid = tid >> 5;
    const int warp_row = wid >> 1;
    const int warp_col = wid & 1;
    const int m0 = blockIdx.y * 128;
    const int n0 = blockIdx.x * 128;
    const uint32_t smem_base = smem_to_u32(smem);

    int rowC[4], c8[4];
    uint32_t sOffT[4];
#pragma unroll
    for (int i = 0; i < 4; ++i) {
        int ch = i * 128 + tid;
        rowC[i] = ch >> 2;
        c8[i] = ch & 3;
        sOffT[i] = (uint32_t)((c8[i] >> 1) * G_SLAB + rowC[i] * G_ROWB +
                              (c8[i] & 1) * 16);
    }

    const uint32_t aLM = (uint32_t)((warp_row * 64 + (lane & 15)) * G_ROWB +
                                    (lane >> 4) * 16);
    const uint32_t bLM = (uint32_t)((warp_col * 64 + ((lane >> 4) << 3) +
                                     (lane & 7)) * G_ROWB +
                                    ((lane >> 3) & 1) * 16);

    auto fill_stage = [&](int stage, int k0) {
        char* base = smem + stage * G_STAGE;
#pragma unroll
        for (int i = 0; i < 4; ++i) {
            const float* gp = X + (size_t)(m0 + rowC[i]) * K + k0 + c8[i] * 8;
            float4 v0 = *(const float4*)gp;
            float4 v1 = *(const float4*)(gp + 4);
            uint32_t hbuf[4], lbuf[4];
            hbuf[0] = packbf(v0.x, v0.y);
            hbuf[1] = packbf(v0.z, v0.w);
            hbuf[2] = packbf(v1.x, v1.y);
            hbuf[3] = packbf(v1.z, v1.w);
            lbuf[0] = packbf(bfres(v0.x), bfres(v0.y));
            lbuf[1] = packbf(bfres(v0.z), bfres(v0.w));
            lbuf[2] = packbf(bfres(v1.x), bfres(v1.y));
            lbuf[3] = packbf(bfres(v1.z), bfres(v1.w));
            const size_t gb = (size_t)(n0 + rowC[i]) * K + k0 + c8[i] * 8;
            uint4 bh = *(const uint4*)(Bhi + gb);
            uint4 bl = *(const uint4*)(Blo + gb);
            *(uint4*)(base + G_T_AHI + sOffT[i]) = *(uint4*)hbuf;
            *(uint4*)(base + G_T_ALO + sOffT[i]) = *(uint4*)lbuf;
            *(uint4*)(base + G_T_BHI + sOffT[i]) = bh;
            *(uint4*)(base + G_T_BLO + sOffT[i]) = bl;
        }
    };

    float acc[4][8][4];
#pragma unroll
    for (int mf = 0; mf < 4; ++mf)
#pragma unroll
        for (int nf = 0; nf < 8; ++nf)
#pragma unroll
            for (int q = 0; q < 4; ++q) acc[mf][nf][q] = 0.f;

    fill_stage(0, 0);
    __syncthreads();

    const int T = K / 32;
    for (int t = 0; t < T; ++t) {
        const int cur = t & 1;
        const uint32_t sb = smem_base + cur * G_STAGE;
#pragma unroll
        for (int kf = 0; kf < 2; ++kf) {
            const uint32_t kfo = kf * G_SLAB;
            uint32_t ah[4][4], al[4][4];
#pragma unroll
            for (int mf = 0; mf < 4; ++mf) {
                ldm4(ah[mf], sb + G_T_AHI + kfo + aLM + mf * 16 * G_ROWB);
                ldm4(al[mf], sb + G_T_ALO + kfo + aLM + mf * 16 * G_ROWB);
            }
#pragma unroll
            for (int pr = 0; pr < 4; ++pr) {
                uint32_t rh[4], rl[4];
                ldm4(rh, sb + G_T_BHI + kfo + bLM + pr * 16 * G_ROWB);
                ldm4(rl, sb + G_T_BLO + kfo + bLM + pr * 16 * G_ROWB);
                uint32_t bh0[2] = {rh[0], rh[1]}, bh1[2] = {rh[2], rh[3]};
                uint32_t bl0[2] = {rl[0], rl[1]}, bl1[2] = {rl[2], rl[3]};
#pragma unroll
                for (int mf = 0; mf < 4; ++mf) {
                    mma_bf16(acc[mf][pr * 2], ah[mf], bh0);
                    mma_bf16(acc[mf][pr * 2], ah[mf], bl0);
                    mma_bf16(acc[mf][pr * 2], al[mf], bh0);
                    mma_bf16(acc[mf][pr * 2 + 1], ah[mf], bh1);
                    mma_bf16(acc[mf][pr * 2 + 1], ah[mf], bl1);
                    mma_bf16(acc[mf][pr * 2 + 1], al[mf], bh1);
                }
            }
        }

        if (t + 1 < T) fill_stage(cur ^ 1, (t + 1) * 32);
        __syncthreads();
    }

    const int mBase = m0 + warp_row * 64 + (lane >> 2);
    const int nBase = n0 + warp_col * 64 + (lane & 3) * 2;
#pragma unroll
    for (int mf = 0; mf < 4; ++mf)
#pragma unroll
        for (int nf = 0; nf < 8; ++nf) {
            const int gm = mBase + mf * 16;
            const int gn = nBase + nf * 8;
            const float* a = acc[mf][nf];
            *(uint32_t*)&Chi[(size_t)gm * Nout + gn] = packbf(a[0], a[1]);
            *(uint32_t*)&Clo[(size_t)gm * Nout + gn] = packbf(bfres(a[0]), bfres(a[1]));
            *(uint32_t*)&Chi[(size_t)(gm + 8) * Nout + gn] = packbf(a[2], a[3]);
            *(uint32_t*)&Clo[(size_t)(gm + 8) * Nout + gn] = packbf(bfres(a[2]), bfres(a[3]));
        }
}

// ---------------------------------------------------------------------------
// Flash attention: persistent Q smem region (frags ldm4'd per iteration,
// R8-style register pressure), double-buffered K/V, ONE __syncthreads per
// iteration, fill after compute. CTA = 128 Q rows x one (b,h), 8 warps.
// ---------------------------------------------------------------------------
#define FM_ROWB 144
#define FQ_HI   0
#define FQ_LO   18432
#define FQ_BYTES 36864
#define FS_KHI  0
#define FS_KLO  9216
#define FS_VHI  18432
#define FS_VLO  27648
#define FS_STAGE 36864
#define FM_SMEM (FQ_BYTES + 2 * FS_STAGE)   // 110592

__global__ __launch_bounds__(256, 2)
void flash_mma(const __nv_bfloat16* __restrict__ Qhi,
               const __nv_bfloat16* __restrict__ Qlo,
               const __nv_bfloat16* __restrict__ Khi,
               const __nv_bfloat16* __restrict__ Klo,
               const __nv_bfloat16* __restrict__ Vhi,
               const __nv_bfloat16* __restrict__ Vlo,
               float* __restrict__ Out, int S, int H)
{
    extern __shared__ char sm[];
    const uint32_t sb = smem_to_u32(sm);
    const int tid = threadIdx.x;
    const int lane = tid & 31;
    const int w = tid >> 5;
    const int D = H * 64;

    const int qblk = blockIdx.x;
    const int bh = blockIdx.y;
    const int b = bh / H;
    const int h = bh % H;

    const size_t qrow0 = (size_t)(b * S + qblk * 128);
    const size_t krow0 = (size_t)(b * S);

    // frag patterns (hardware-validated rounds 4-8)
    const uint32_t aOff = (uint32_t)((w * 16 + (lane & 15)) * FM_ROWB +
                                     ((lane >> 4) << 4));
    const uint32_t bRow = ((lane >> 4) << 3) + (lane & 7);
    const uint32_t bSeg = ((lane >> 3) & 1) << 4;

    // K/V stage fill (stages live after the persistent Q region)
    auto fill_kv = [&](int stage, int kv) {
        char* base = sm + FQ_BYTES + stage * FS_STAGE;
        const __nv_bfloat16* Kh = Khi + (krow0 + kv * 64) * D + h * 64;
        const __nv_bfloat16* Kl = Klo + (krow0 + kv * 64) * D + h * 64;
        const __nv_bfloat16* Vh = Vhi + (krow0 + kv * 64) * D + h * 64;
        const __nv_bfloat16* Vl = Vlo + (krow0 + kv * 64) * D + h * 64;
#pragma unroll
        for (int i = 0; i < 2; ++i) {
            const int ch = i * 256 + tid;        // 0..511
            const int row = ch >> 3;             // j
            const int c = ch & 7;
            *(uint4*)(base + FS_KHI + row * FM_ROWB + c * 16) =
                *(const uint4*)(Kh + (size_t)row * D + c * 8);
            *(uint4*)(base + FS_KLO + row * FM_ROWB + c * 16) =
                *(const uint4*)(Kl + (size_t)row * D + c * 8);
            uint4 vh = *(const uint4*)(Vh + (size_t)row * D + c * 8);
            uint4 vl = *(const uint4*)(Vl + (size_t)row * D + c * 8);
            const unsigned short* ph = (const unsigned short*)&vh;
            const unsigned short* pl = (const unsigned short*)&vl;
#pragma unroll
            for (int u = 0; u < 8; ++u) {
                *(unsigned short*)(base + FS_VHI + (c * 8 + u) * FM_ROWB + row * 2) = ph[u];
                *(unsigned short*)(base + FS_VLO + (c * 8 + u) * FM_ROWB + row * 2) = pl[u];
            }
        }
    };

    // ---- prologue: stage Q (persistent) and K/V stage 0, one barrier ----
    {
        const __nv_bfloat16* Qh = Qhi + qrow0 * D + h * 64;
        const __nv_bfloat16* Ql = Qlo + qrow0 * D + h * 64;
#pragma unroll
        for (int i = 0; i < 4; ++i) {
            const int ch = i * 256 + tid;        // 0..1023
            const int row = ch >> 3;
            const int c = ch & 7;
            *(uint4*)(sm + FQ_HI + row * FM_ROWB + c * 16) =
                *(const uint4*)(Qh + (size_t)row * D + c * 8);
            *(uint4*)(sm + FQ_LO + row * FM_ROWB + c * 16) =
                *(const uint4*)(Ql + (size_t)row * D + c * 8);
        }
    }
    fill_kv(0, 0);
    __syncthreads();

    float o[8][4];
    float sacc[8][4];
#pragma unroll
    for (int nf = 0; nf < 8; ++nf)
#pragma unroll
        for (int q = 0; q < 4; ++q) o[nf][q] = 0.f;
    float m0v = -1e30f, m1v = -1e30f, l0v = 0.f, l1v = 0.f;

    const float qs = 0.125f * 1.4426950408889634f;
    const int nkv = S / 64;

    for (int kv = 0; kv < nkv; ++kv) {
        const int cur = kv & 1;
        const uint32_t stg = sb + FQ_BYTES + cur * FS_STAGE;

        // ---- S = Q K^T (Q frags ldm4'd per iteration from persistent smem) ----
#pragma unroll
        for (int nf = 0; nf < 8; ++nf)
#pragma unroll
            for (int q = 0; q < 4; ++q) sacc[nf][q] = 0.f;

#pragma unroll
        for (int kf = 0; kf < 4; ++kf) {
            uint32_t qh[4], ql[4];
            ldm4(qh, sb + FQ_HI + aOff + kf * 32);
            ldm4(ql, sb + FQ_LO + aOff + kf * 32);
#pragma unroll
            for (int pr = 0; pr < 4; ++pr) {
                uint32_t rh[4], rl[4];
                ldm4(rh, stg + FS_KHI + (pr * 16 + bRow) * FM_ROWB + kf * 32 + bSeg);
                ldm4(rl, stg + FS_KLO + (pr * 16 + bRow) * FM_ROWB + kf * 32 + bSeg);
                uint32_t bh0[2] = {rh[0], rh[1]}, bh1[2] = {rh[2], rh[3]};
                uint32_t bl0[2] = {rl[0], rl[1]}, bl1[2] = {rl[2], rl[3]};
                mma_bf16(sacc[pr * 2], qh, bh0);
                mma_bf16(sacc[pr * 2], qh, bl0);
                mma_bf16(sacc[pr * 2], ql, bh0);
                mma_bf16(sacc[pr * 2 + 1], qh, bh1);
                mma_bf16(sacc[pr * 2 + 1], qh, bl1);
                mma_bf16(sacc[pr * 2 + 1], ql, bh1);
            }
        }

        // ---- online softmax ----
        float rm0 = -1e30f, rm1 = -1e30f;
#pragma unroll
        for (int nf = 0; nf < 8; ++nf) {
#pragma unroll
            for (int q = 0; q < 4; ++q) sacc[nf][q] *= qs;
            rm0 = fmaxf(rm0, fmaxf(sacc[nf][0], sacc[nf][1]));
            rm1 = fmaxf(rm1, fmaxf(sacc[nf][2], sacc[nf][3]));
        }
        rm0 = fmaxf(rm0, __shfl_xor_sync(0xffffffffu, rm0, 1));
        rm0 = fmaxf(rm0, __shfl_xor_sync(0xffffffffu, rm0, 2));
        rm1 = fmaxf(rm1, __shfl_xor_sync(0xffffffffu, rm1, 1));
        rm1 = fmaxf(rm1, __shfl_xor_sync(0xffffffffu, rm1, 2));

        const float mn0 = fmaxf(m0v, rm0);
        const float mn1 = fmaxf(m1v, rm1);
        const float a0 = exp2f(m0v - mn0);
        const float a1 = exp2f(m1v - mn1);
        float rs0 = 0.f, rs1 = 0.f;
#pragma unroll
        for (int nf = 0; nf < 8; ++nf) {
            float p0 = exp2f(sacc[nf][0] - mn0);
            float p1 = exp2f(sacc[nf][1] - mn0);
            float p2 = exp2f(sacc[nf][2] - mn1);
            float p3 = exp2f(sacc[nf][3] - mn1);
            sacc[nf][0] = p0; sacc[nf][1] = p1;
            sacc[nf][2] = p2; sacc[nf][3] = p3;
            rs0 += p0 + p1;
            rs1 += p2 + p3;
        }
        rs0 += __shfl_xor_sync(0xffffffffu, rs0, 1);
        rs0 += __shfl_xor_sync(0xffffffffu, rs0, 2);
        rs1 += __shfl_xor_sync(0xffffffffu, rs1, 1);
        rs1 += __shfl_xor_sync(0xffffffffu, rs1, 2);
        l0v = l0v * a0 + rs0;
        l1v = l1v * a1 + rs1;
        m0v = mn0; m1v = mn1;
#pragma unroll
        for (int nf = 0; nf < 8; ++nf) {
            o[nf][0] *= a0; o[nf][1] *= a0;
            o[nf][2] *= a1; o[nf][3] *= a1;
        }

        // ---- O += P V ----
#pragma unroll
        for (int jf = 0; jf < 4; ++jf) {
            const float* p0 = sacc[2 * jf];
            const float* p1 = sacc[2 * jf + 1];
            uint32_t aph[4], apl[4];
            aph[0] = packbf(p0[0], p0[1]);
            aph[1] = packbf(p0[2], p0[3]);
            aph[2] = packbf(p1[0], p1[1]);
            aph[3] = packbf(p1[2], p1[3]);
            apl[0] = packbf(bfres(p0[0]), bfres(p0[1]));
            apl[1] = packbf(bfres(p0[2]), bfres(p0[3]));
            apl[2] = packbf(bfres(p1[0]), bfres(p1[1]));
            apl[3] = packbf(bfres(p1[2]), bfres(p1[3]));
#pragma unroll
            for (int pr = 0; pr < 4; ++pr) {
                uint32_t rv[4], rl[4];
                ldm4(rv, stg + FS_VHI + (pr * 16 + bRow) * FM_ROWB + jf * 32 + bSeg);
                ldm4(rl, stg + FS_VLO + (pr * 16 + bRow) * FM_ROWB + jf * 32 + bSeg);
                uint32_t bvh0[2] = {rv[0], rv[1]}, bvh1[2] = {rv[2], rv[3]};
                uint32_t bvl0[2] = {rl[0], rl[1]}, bvl1[2] = {rl[2], rl[3]};
                mma_bf16(o[pr * 2], aph, bvh0);
                mma_bf16(o[pr * 2], aph, bvl0);
                mma_bf16(o[pr * 2], apl, bvh0);
                mma_bf16(o[pr * 2 + 1], aph, bvh1);
                mma_bf16(o[pr * 2 + 1], aph, bvl1);
                mma_bf16(o[pr * 2 + 1], apl, bvh1);
            }
        }

        // ---- fill next stage (loads hoistable above the MMA blocks) ----
        if (kv + 1 < nkv) fill_kv(cur ^ 1, kv + 1);
        __syncthreads();
    }

    // ---- epilogue ----
    const float inv0 = 1.f / l0v;
    const float inv1 = 1.f / l1v;
    const int r0 = lane >> 2;
    const int c2 = (lane & 3) * 2;
    float* O0 = Out + (qrow0 + w * 16 + r0) * D + h * 64;
#pragma unroll
    for (int nf = 0; nf < 8; ++nf) {
        *(float2*)(O0 + nf * 8 + c2) =
            make_float2(o[nf][0] * inv0, o[nf][1] * inv0);
        *(float2*)(O0 + (size_t)8 * D + nf * 8 + c2) =
            make_float2(o[nf][2] * inv1, o[nf][3] * inv1);
    }
}

// ----------------------------------------------------------------------------
// Launch
// ----------------------------------------------------------------------------
extern "C" void kernel_launch(void* const* d_in, const int* in_sizes, int n_in,
                              void* d_out, int out_size)
{
    const float* x[3] = {(const float*)d_in[0], (const float*)d_in[1],
                         (const float*)d_in[2]};
    const float* w[3] = {(const float*)d_in[3], (const float*)d_in[4],
                         (const float*)d_in[5]};
    float* out = (float*)d_out;

    const int D = MHA_D, M = MHA_M, S = MHA_S, H = MHA_H;
    const int B = M / S;

    __nv_bfloat16 *Qhi, *Qlo, *Khi, *Klo, *Vhi, *Vlo, *Bhi, *Blo;
    cudaGetSymbolAddress((void**)&Qhi, g_Qhi);
    cudaGetSymbolAddress((void**)&Qlo, g_Qlo);
    cudaGetSymbolAddress((void**)&Khi, g_Khi);
    cudaGetSymbolAddress((void**)&Klo, g_Klo);
    cudaGetSymbolAddress((void**)&Vhi, g_Vhi);
    cudaGetSymbolAddress((void**)&Vlo, g_Vlo);
    cudaGetSymbolAddress((void**)&Bhi, g_Bhi);
    cudaGetSymbolAddress((void**)&Blo, g_Blo);

    __nv_bfloat16* outs_hi[3] = {Qhi, Khi, Vhi};
    __nv_bfloat16* outs_lo[3] = {Qlo, Klo, Vlo};

    cudaFuncSetAttribute(gemm_fused,
                         cudaFuncAttributeMaxDynamicSharedMemorySize, GEMM_SMEM);
    cudaFuncSetAttribute(flash_mma,
                         cudaFuncAttributeMaxDynamicSharedMemorySize, FM_SMEM);

    for (int p = 0; p < 3; ++p) {
        transpose_split<<<dim3(D / 32, D / 32), dim3(32, 8)>>>(w[p], Bhi, Blo, D);
        gemm_fused<<<dim3(D / 128, M / 128), 128, GEMM_SMEM>>>(
            x[p], Bhi, Blo, outs_hi[p], outs_lo[p], D, D);
    }

    dim3 fg(S / 128, B * H);
    flash_mma<<<fg, 256, FM_SMEM>>>(Qhi, Qlo, Khi, Klo, Vhi, Vlo, out, S, H);
}

// round 16
// speedup vs baseline: 1.2208x; 1.0418x over previous
#include <cuda_runtime.h>
#include <cuda_bf16.h>
#include <math.h>
#include <cstdint>

// ============================================================================
// MHA: out = softmax((XqWq)(XkWk)^T / sqrt(Hd)) (XvWv)
// B=8, S=1024, D=1024, H=16, Hd=64, fp32 in/out. Plain sm_100 (no tcgen05).
//
// Round 16: batched launches only — all 3 weight transposes in one launch
// (grid.z=3) and all 3 projection GEMMs in one launch (grid.z=3). MMA
// ordering is exactly the R14-proven sequence (no interleave experiment).
// Flash attention = R14 passing version, unchanged.
// ============================================================================

#define MHA_M   8192
#define MHA_D   1024
#define MHA_H   16
#define MHA_S   1024

__device__ __nv_bfloat16 g_Qhi[MHA_M * MHA_D];
__device__ __nv_bfloat16 g_Qlo[MHA_M * MHA_D];
__device__ __nv_bfloat16 g_Khi[MHA_M * MHA_D];
__device__ __nv_bfloat16 g_Klo[MHA_M * MHA_D];
__device__ __nv_bfloat16 g_Vhi[MHA_M * MHA_D];
__device__ __nv_bfloat16 g_Vlo[MHA_M * MHA_D];
__device__ __nv_bfloat16 g_Bhi[3 * MHA_D * MHA_D];   // W^T x3, [N][K]
__device__ __nv_bfloat16 g_Blo[3 * MHA_D * MHA_D];

// ---------------------------------------------------------------------------
// helpers
// ---------------------------------------------------------------------------
__device__ __forceinline__ uint32_t smem_to_u32(const void* p) {
    uint32_t a;
    asm("{ .reg .u64 t; cvta.to.shared.u64 t, %1; cvt.u32.u64 %0, t; }"
        : "=r"(a) : "l"(p));
    return a;
}
__device__ __forceinline__ void ldm4(uint32_t* r, uint32_t addr) {
    asm volatile("ldmatrix.sync.aligned.m8n8.x4.shared.b16 {%0,%1,%2,%3}, [%4];"
                 : "=r"(r[0]), "=r"(r[1]), "=r"(r[2]), "=r"(r[3]) : "r"(addr));
}
__device__ __forceinline__ void mma_bf16(float* d, const uint32_t* a,
                                         const uint32_t* b) {
    asm volatile(
        "mma.sync.aligned.m16n8k16.row.col.f32.bf16.bf16.f32 "
        "{%0,%1,%2,%3}, {%4,%5,%6,%7}, {%8,%9}, {%0,%1,%2,%3};"
        : "+f"(d[0]), "+f"(d[1]), "+f"(d[2]), "+f"(d[3])
        : "r"(a[0]), "r"(a[1]), "r"(a[2]), "r"(a[3]), "r"(b[0]), "r"(b[1]));
}
__device__ __forceinline__ uint32_t packbf(float x, float y) {
    __nv_bfloat162 t = __floats2bfloat162_rn(x, y);
    return *reinterpret_cast<uint32_t*>(&t);
}
__device__ __forceinline__ float bfres(float x) {
    return x - __bfloat162float(__float2bfloat16_rn(x));
}

// ---------------------------------------------------------------------------
// W [K,N] fp32 -> W^T [N,K] bf16 hi/lo, all 3 weights in one launch (z).
// ---------------------------------------------------------------------------
__global__ void transpose_split3(const float* __restrict__ W0,
                                 const float* __restrict__ W1,
                                 const float* __restrict__ W2,
                                 __nv_bfloat16* __restrict__ hi,
                                 __nv_bfloat16* __restrict__ lo, int Dm)
{
    __shared__ float t[32][33];
    const int p = blockIdx.z;
    const float* W = (p == 0) ? W0 : (p == 1) ? W1 : W2;
    __nv_bfloat16* hip = hi + (size_t)p * Dm * Dm;
    __nv_bfloat16* lop = lo + (size_t)p * Dm * Dm;

    const int bx = blockIdx.x * 32;
    const int by = blockIdx.y * 32;
    const int x = threadIdx.x, y = threadIdx.y;
#pragma unroll
    for (int j = 0; j < 4; ++j)
        t[y + 8 * j][x] = W[(size_t)(by + y + 8 * j) * Dm + bx + x];
    __syncthreads();
#pragma unroll
    for (int j = 0; j < 4; ++j) {
        float v = t[x][y + 8 * j];
        __nv_bfloat16 h = __float2bfloat16(v);
        __nv_bfloat16 l = __float2bfloat16(v - __bfloat162float(h));
        size_t o = (size_t)(bx + y + 8 * j) * Dm + by + x;
        hip[o] = h;
        lop[o] = l;
    }
}

// ---------------------------------------------------------------------------
// Projection GEMM, all 3 projections in one launch (grid.z selects p).
// A = fp32 X (converted to hi/lo in-kernel), B = bf16 hi/lo.
// CTA 128x128, BK=32, 128 threads = 4 warps (2x2 grid of 64x64 warp tiles).
// MMA body identical to the R14 passing kernel.
// ---------------------------------------------------------------------------
#define G_ROWB  48
#define G_SLAB  (128 * G_ROWB)          // 6144
#define G_T_AHI 0
#define G_T_ALO (2 * G_SLAB)
#define G_T_BHI (4 * G_SLAB)
#define G_T_BLO (6 * G_SLAB)
#define G_STAGE (8 * G_SLAB)            // 49152
#define GEMM_SMEM (2 * G_STAGE)         // 98304

__global__ __launch_bounds__(128, 2)
void gemm_fused3(const float* __restrict__ X0,
                 const float* __restrict__ X1,
                 const float* __restrict__ X2,
                 const __nv_bfloat16* __restrict__ BhiAll,
                 const __nv_bfloat16* __restrict__ BloAll,
                 __nv_bfloat16* __restrict__ Qhi, __nv_bfloat16* __restrict__ Qlo,
                 __nv_bfloat16* __restrict__ Khi, __nv_bfloat16* __restrict__ Klo,
                 __nv_bfloat16* __restrict__ Vhi, __nv_bfloat16* __restrict__ Vlo,
                 int K, int Nout)
{
    extern __shared__ char smem[];
    const int p = blockIdx.z;
    const float* X = (p == 0) ? X0 : (p == 1) ? X1 : X2;
    const __nv_bfloat16* Bhi = BhiAll + (size_t)p * K * Nout;
    const __nv_bfloat16* Blo = BloAll + (size_t)p * K * Nout;
    __nv_bfloat16* Chi = (p == 0) ? Qhi : (p == 1) ? Khi : Vhi;
    __nv_bfloat16* Clo = (p == 0) ? Qlo : (p == 1) ? Klo : Vlo;

    const int tid = threadIdx.x;
    const int lane = tid & 31;
    const int wid = tid >> 5;
    const int warp_row = wid >> 1;
    const int warp_col = wid & 1;
    const int m0 = blockIdx.y * 128;
    const int n0 = blockIdx.x * 128;
    const uint32_t smem_base = smem_to_u32(smem);

    int rowC[4], c8[4];
    uint32_t sOffT[4];
#pragma unroll
    for (int i = 0; i < 4; ++i) {
        int ch = i * 128 + tid;
        rowC[i] = ch >> 2;
        c8[i] = ch & 3;
        sOffT[i] = (uint32_t)((c8[i] >> 1) * G_SLAB + rowC[i] * G_ROWB +
                              (c8[i] & 1) * 16);
    }

    const uint32_t aLM = (uint32_t)((warp_row * 64 + (lane & 15)) * G_ROWB +
                                    (lane >> 4) * 16);
    const uint32_t bLM = (uint32_t)((warp_col * 64 + ((lane >> 4) << 3) +
                                     (lane & 7)) * G_ROWB +
                                    ((lane >> 3) & 1) * 16);

    auto fill_stage = [&](int stage, int k0) {
        char* base = smem + stage * G_STAGE;
#pragma unroll
        for (int i = 0; i < 4; ++i) {
            const float* gp = X + (size_t)(m0 + rowC[i]) * K + k0 + c8[i] * 8;
            float4 v0 = *(const float4*)gp;
            float4 v1 = *(const float4*)(gp + 4);
            uint32_t hbuf[4], lbuf[4];
            hbuf[0] = packbf(v0.x, v0.y);
            hbuf[1] = packbf(v0.z, v0.w);
            hbuf[2] = packbf(v1.x, v1.y);
            hbuf[3] = packbf(v1.z, v1.w);
            lbuf[0] = packbf(bfres(v0.x), bfres(v0.y));
            lbuf[1] = packbf(bfres(v0.z), bfres(v0.w));
            lbuf[2] = packbf(bfres(v1.x), bfres(v1.y));
            lbuf[3] = packbf(bfres(v1.z), bfres(v1.w));
            const size_t gb = (size_t)(n0 + rowC[i]) * K + k0 + c8[i] * 8;
            uint4 bh = *(const uint4*)(Bhi + gb);
            uint4 bl = *(const uint4*)(Blo + gb);
            *(uint4*)(base + G_T_AHI + sOffT[i]) = *(uint4*)hbuf;
            *(uint4*)(base + G_T_ALO + sOffT[i]) = *(uint4*)lbuf;
            *(uint4*)(base + G_T_BHI + sOffT[i]) = bh;
            *(uint4*)(base + G_T_BLO + sOffT[i]) = bl;
        }
    };

    float acc[4][8][4];
#pragma unroll
    for (int mf = 0; mf < 4; ++mf)
#pragma unroll
        for (int nf = 0; nf < 8; ++nf)
#pragma unroll
            for (int q = 0; q < 4; ++q) acc[mf][nf][q] = 0.f;

    fill_stage(0, 0);
    __syncthreads();

    const int T = K / 32;
    for (int t = 0; t < T; ++t) {
        const int cur = t & 1;
        const uint32_t sb = smem_base + cur * G_STAGE;
#pragma unroll
        for (int kf = 0; kf < 2; ++kf) {
            const uint32_t kfo = kf * G_SLAB;
            uint32_t ah[4][4], al[4][4];
#pragma unroll
            for (int mf = 0; mf < 4; ++mf) {
                ldm4(ah[mf], sb + G_T_AHI + kfo + aLM + mf * 16 * G_ROWB);
                ldm4(al[mf], sb + G_T_ALO + kfo + aLM + mf * 16 * G_ROWB);
            }
#pragma unroll
            for (int pr = 0; pr < 4; ++pr) {
                uint32_t rh[4], rl[4];
                ldm4(rh, sb + G_T_BHI + kfo + bLM + pr * 16 * G_ROWB);
                ldm4(rl, sb + G_T_BLO + kfo + bLM + pr * 16 * G_ROWB);
                uint32_t bh0[2] = {rh[0], rh[1]}, bh1[2] = {rh[2], rh[3]};
                uint32_t bl0[2] = {rl[0], rl[1]}, bl1[2] = {rl[2], rl[3]};
#pragma unroll
                for (int mf = 0; mf < 4; ++mf) {
                    mma_bf16(acc[mf][pr * 2], ah[mf], bh0);
                    mma_bf16(acc[mf][pr * 2], ah[mf], bl0);
                    mma_bf16(acc[mf][pr * 2], al[mf], bh0);
                    mma_bf16(acc[mf][pr * 2 + 1], ah[mf], bh1);
                    mma_bf16(acc[mf][pr * 2 + 1], ah[mf], bl1);
                    mma_bf16(acc[mf][pr * 2 + 1], al[mf], bh1);
                }
            }
        }

        if (t + 1 < T) fill_stage(cur ^ 1, (t + 1) * 32);
        __syncthreads();
    }

    const int mBase = m0 + warp_row * 64 + (lane >> 2);
    const int nBase = n0 + warp_col * 64 + (lane & 3) * 2;
#pragma unroll
    for (int mf = 0; mf < 4; ++mf)
#pragma unroll
        for (int nf = 0; nf < 8; ++nf) {
            const int gm = mBase + mf * 16;
            const int gn = nBase + nf * 8;
            const float* a = acc[mf][nf];
            *(uint32_t*)&Chi[(size_t)gm * Nout + gn] = packbf(a[0], a[1]);
            *(uint32_t*)&Clo[(size_t)gm * Nout + gn] = packbf(bfres(a[0]), bfres(a[1]));
            *(uint32_t*)&Chi[(size_t)(gm + 8) * Nout + gn] = packbf(a[2], a[3]);
            *(uint32_t*)&Clo[(size_t)(gm + 8) * Nout + gn] = packbf(bfres(a[2]), bfres(a[3]));
        }
}

// ---------------------------------------------------------------------------
// Flash attention (identical to the R14 passing kernel).
// Persistent Q smem region, double-buffered K/V, one __syncthreads per iter.
// ---------------------------------------------------------------------------
#define FM_ROWB 144
#define FQ_HI   0
#define FQ_LO   18432
#define FQ_BYTES 36864
#define FS_KHI  0
#define FS_KLO  9216
#define FS_VHI  18432
#define FS_VLO  27648
#define FS_STAGE 36864
#define FM_SMEM (FQ_BYTES + 2 * FS_STAGE)   // 110592

__global__ __launch_bounds__(256, 2)
void flash_mma(const __nv_bfloat16* __restrict__ Qhi,
               const __nv_bfloat16* __restrict__ Qlo,
               const __nv_bfloat16* __restrict__ Khi,
               const __nv_bfloat16* __restrict__ Klo,
               const __nv_bfloat16* __restrict__ Vhi,
               const __nv_bfloat16* __restrict__ Vlo,
               float* __restrict__ Out, int S, int H)
{
    extern __shared__ char sm[];
    const uint32_t sb = smem_to_u32(sm);
    const int tid = threadIdx.x;
    const int lane = tid & 31;
    const int w = tid >> 5;
    const int D = H * 64;

    const int qblk = blockIdx.x;
    const int bh = blockIdx.y;
    const int b = bh / H;
    const int h = bh % H;

    const size_t qrow0 = (size_t)(b * S + qblk * 128);
    const size_t krow0 = (size_t)(b * S);

    const uint32_t aOff = (uint32_t)((w * 16 + (lane & 15)) * FM_ROWB +
                                     ((lane >> 4) << 4));
    const uint32_t bRow = ((lane >> 4) << 3) + (lane & 7);
    const uint32_t bSeg = ((lane >> 3) & 1) << 4;

    auto fill_kv = [&](int stage, int kv) {
        char* base = sm + FQ_BYTES + stage * FS_STAGE;
        const __nv_bfloat16* Kh = Khi + (krow0 + kv * 64) * D + h * 64;
        const __nv_bfloat16* Kl = Klo + (krow0 + kv * 64) * D + h * 64;
        const __nv_bfloat16* Vh = Vhi + (krow0 + kv * 64) * D + h * 64;
        const __nv_bfloat16* Vl = Vlo + (krow0 + kv * 64) * D + h * 64;
#pragma unroll
        for (int i = 0; i < 2; ++i) {
            const int ch = i * 256 + tid;
            const int row = ch >> 3;
            const int c = ch & 7;
            *(uint4*)(base + FS_KHI + row * FM_ROWB + c * 16) =
                *(const uint4*)(Kh + (size_t)row * D + c * 8);
            *(uint4*)(base + FS_KLO + row * FM_ROWB + c * 16) =
                *(const uint4*)(Kl + (size_t)row * D + c * 8);
            uint4 vh = *(const uint4*)(Vh + (size_t)row * D + c * 8);
            uint4 vl = *(const uint4*)(Vl + (size_t)row * D + c * 8);
            const unsigned short* ph = (const unsigned short*)&vh;
            const unsigned short* pl = (const unsigned short*)&vl;
#pragma unroll
            for (int u = 0; u < 8; ++u) {
                *(unsigned short*)(base + FS_VHI + (c * 8 + u) * FM_ROWB + row * 2) = ph[u];
                *(unsigned short*)(base + FS_VLO + (c * 8 + u) * FM_ROWB + row * 2) = pl[u];
            }
        }
    };

    // prologue: stage Q (persistent) and K/V stage 0
    {
        const __nv_bfloat16* Qh = Qhi + qrow0 * D + h * 64;
        const __nv_bfloat16* Ql = Qlo + qrow0 * D + h * 64;
#pragma unroll
        for (int i = 0; i < 4; ++i) {
            const int ch = i * 256 + tid;
            const int row = ch >> 3;
            const int c = ch & 7;
            *(uint4*)(sm + FQ_HI + row * FM_ROWB + c * 16) =
                *(const uint4*)(Qh + (size_t)row * D + c * 8);
            *(uint4*)(sm + FQ_LO + row * FM_ROWB + c * 16) =
                *(const uint4*)(Ql + (size_t)row * D + c * 8);
        }
    }
    fill_kv(0, 0);
    __syncthreads();

    float o[8][4];
    float sacc[8][4];
#pragma unroll
    for (int nf = 0; nf < 8; ++nf)
#pragma unroll
        for (int q = 0; q < 4; ++q) o[nf][q] = 0.f;
    float m0v = -1e30f, m1v = -1e30f, l0v = 0.f, l1v = 0.f;

    const float qs = 0.125f * 1.4426950408889634f;
    const int nkv = S / 64;

    for (int kv = 0; kv < nkv; ++kv) {
        const int cur = kv & 1;
        const uint32_t stg = sb + FQ_BYTES + cur * FS_STAGE;

#pragma unroll
        for (int nf = 0; nf < 8; ++nf)
#pragma unroll
            for (int q = 0; q < 4; ++q) sacc[nf][q] = 0.f;

#pragma unroll
        for (int kf = 0; kf < 4; ++kf) {
            uint32_t qh[4], ql[4];
            ldm4(qh, sb + FQ_HI + aOff + kf * 32);
            ldm4(ql, sb + FQ_LO + aOff + kf * 32);
#pragma unroll
            for (int pr = 0; pr < 4; ++pr) {
                uint32_t rh[4], rl[4];
                ldm4(rh, stg + FS_KHI + (pr * 16 + bRow) * FM_ROWB + kf * 32 + bSeg);
                ldm4(rl, stg + FS_KLO + (pr * 16 + bRow) * FM_ROWB + kf * 32 + bSeg);
                uint32_t bh0[2] = {rh[0], rh[1]}, bh1[2] = {rh[2], rh[3]};
                uint32_t bl0[2] = {rl[0], rl[1]}, bl1[2] = {rl[2], rl[3]};
                mma_bf16(sacc[pr * 2], qh, bh0);
                mma_bf16(sacc[pr * 2], qh, bl0);
                mma_bf16(sacc[pr * 2], ql, bh0);
                mma_bf16(sacc[pr * 2 + 1], qh, bh1);
                mma_bf16(sacc[pr * 2 + 1], qh, bl1);
                mma_bf16(sacc[pr * 2 + 1], ql, bh1);
            }
        }

        float rm0 = -1e30f, rm1 = -1e30f;
#pragma unroll
        for (int nf = 0; nf < 8; ++nf) {
#pragma unroll
            for (int q = 0; q < 4; ++q) sacc[nf][q] *= qs;
            rm0 = fmaxf(rm0, fmaxf(sacc[nf][0], sacc[nf][1]));
            rm1 = fmaxf(rm1, fmaxf(sacc[nf][2], sacc[nf][3]));
        }
        rm0 = fmaxf(rm0, __shfl_xor_sync(0xffffffffu, rm0, 1));
        rm0 = fmaxf(rm0, __shfl_xor_sync(0xffffffffu, rm0, 2));
        rm1 = fmaxf(rm1, __shfl_xor_sync(0xffffffffu, rm1, 1));
        rm1 = fmaxf(rm1, __shfl_xor_sync(0xffffffffu, rm1, 2));

        const float mn0 = fmaxf(m0v, rm0);
        const float mn1 = fmaxf(m1v, rm1);
        const float a0 = exp2f(m0v - mn0);
        const float a1 = exp2f(m1v - mn1);
        float rs0 = 0.f, rs1 = 0.f;
#pragma unroll
        for (int nf = 0; nf < 8; ++nf) {
            float p0 = exp2f(sacc[nf][0] - mn0);
            float p1 = exp2f(sacc[nf][1] - mn0);
            float p2 = exp2f(sacc[nf][2] - mn1);
            float p3 = exp2f(sacc[nf][3] - mn1);
            sacc[nf][0] = p0; sacc[nf][1] = p1;
            sacc[nf][2] = p2; sacc[nf][3] = p3;
            rs0 += p0 + p1;
            rs1 += p2 + p3;
        }
        rs0 += __shfl_xor_sync(0xffffffffu, rs0, 1);
        rs0 += __shfl_xor_sync(0xffffffffu, rs0, 2);
        rs1 += __shfl_xor_sync(0xffffffffu, rs1, 1);
        rs1 += __shfl_xor_sync(0xffffffffu, rs1, 2);
        l0v = l0v * a0 + rs0;
        l1v = l1v * a1 + rs1;
        m0v = mn0; m1v = mn1;
#pragma unroll
        for (int nf = 0; nf < 8; ++nf) {
            o[nf][0] *= a0; o[nf][1] *= a0;
            o[nf][2] *= a1; o[nf][3] *= a1;
        }

#pragma unroll
        for (int jf = 0; jf < 4; ++jf) {
            const float* p0 = sacc[2 * jf];
            const float* p1 = sacc[2 * jf + 1];
            uint32_t aph[4], apl[4];
            aph[0] = packbf(p0[0], p0[1]);
            aph[1] = packbf(p0[2], p0[3]);
            aph[2] = packbf(p1[0], p1[1]);
            aph[3] = packbf(p1[2], p1[3]);
            apl[0] = packbf(bfres(p0[0]), bfres(p0[1]));
            apl[1] = packbf(bfres(p0[2]), bfres(p0[3]));
            apl[2] = packbf(bfres(p1[0]), bfres(p1[1]));
            apl[3] = packbf(bfres(p1[2]), bfres(p1[3]));
#pragma unroll
            for (int pr = 0; pr < 4; ++pr) {
                uint32_t rv[4], rl[4];
                ldm4(rv, stg + FS_VHI + (pr * 16 + bRow) * FM_ROWB + jf * 32 + bSeg);
                ldm4(rl, stg + FS_VLO + (pr * 16 + bRow) * FM_ROWB + jf * 32 + bSeg);
                uint32_t bvh0[2] = {rv[0], rv[1]}, bvh1[2] = {rv[2], rv[3]};
                uint32_t bvl0[2] = {rl[0], rl[1]}, bvl1[2] = {rl[2], rl[3]};
                mma_bf16(o[pr * 2], aph, bvh0);
                mma_bf16(o[pr * 2], aph, bvl0);
                mma_bf16(o[pr * 2], apl, bvh0);
                mma_bf16(o[pr * 2 + 1], aph, bvh1);
                mma_bf16(o[pr * 2 + 1], aph, bvl1);
                mma_bf16(o[pr * 2 + 1], apl, bvh1);
            }
        }

        if (kv + 1 < nkv) fill_kv(cur ^ 1, kv + 1);
        __syncthreads();
    }

    const float inv0 = 1.f / l0v;
    const float inv1 = 1.f / l1v;
    const int r0 = lane >> 2;
    const int c2 = (lane & 3) * 2;
    float* O0 = Out + (qrow0 + w * 16 + r0) * D + h * 64;
#pragma unroll
    for (int nf = 0; nf < 8; ++nf) {
        *(float2*)(O0 + nf * 8 + c2) =
            make_float2(o[nf][0] * inv0, o[nf][1] * inv0);
        *(float2*)(O0 + (size_t)8 * D + nf * 8 + c2) =
            make_float2(o[nf][2] * inv1, o[nf][3] * inv1);
    }
}

// ----------------------------------------------------------------------------
// Launch
// ----------------------------------------------------------------------------
extern "C" void kernel_launch(void* const* d_in, const int* in_sizes, int n_in,
                              void* d_out, int out_size)
{
    const float* xq = (const float*)d_in[0];
    const float* xk = (const float*)d_in[1];
    const float* xv = (const float*)d_in[2];
    const float* wq = (const float*)d_in[3];
    const float* wk = (const float*)d_in[4];
    const float* wv = (const float*)d_in[5];
    float* out = (float*)d_out;

    const int D = MHA_D, M = MHA_M, S = MHA_S, H = MHA_H;
    const int B = M / S;

    __nv_bfloat16 *Qhi, *Qlo, *Khi, *Klo, *Vhi, *Vlo, *Bhi, *Blo;
    cudaGetSymbolAddress((void**)&Qhi, g_Qhi);
    cudaGetSymbolAddress((void**)&Qlo, g_Qlo);
    cudaGetSymbolAddress((void**)&Khi, g_Khi);
    cudaGetSymbolAddress((void**)&Klo, g_Klo);
    cudaGetSymbolAddress((void**)&Vhi, g_Vhi);
    cudaGetSymbolAddress((void**)&Vlo, g_Vlo);
    cudaGetSymbolAddress((void**)&Bhi, g_Bhi);
    cudaGetSymbolAddress((void**)&Blo, g_Blo);

    cudaFuncSetAttribute(gemm_fused3,
                         cudaFuncAttributeMaxDynamicSharedMemorySize, GEMM_SMEM);
    cudaFuncSetAttribute(flash_mma,
                         cudaFuncAttributeMaxDynamicSharedMemorySize, FM_SMEM);

    transpose_split3<<<dim3(D / 32, D / 32, 3), dim3(32, 8)>>>(
        wq, wk, wv, Bhi, Blo, D);
    gemm_fused3<<<dim3(D / 128, M / 128, 3), 128, GEMM_SMEM>>>(
        xq, xk, xv, Bhi, Blo, Qhi, Qlo, Khi, Klo, Vhi, Vlo, D, D);

    dim3 fg(S / 128, B * H);
    flash_mma<<<fg, 256, FM_SMEM>>>(Qhi, Qlo, Khi, Klo, Vhi, Vlo, out, S, H);
}